// round 13
// baseline (speedup 1.0000x reference)
#include <cuda_runtime.h>
#include <cuda_fp16.h>

// ----------------------------------------------------------------------------
// GCN-with-skip, 3 layers.  Algebra:
//   A~ x[i] = dinv[i] * ( sum_{e: dst=i} dinv[src] x[src]  +  dinv[i] x[i] )
// With xd = dinv * x:  A~ x[i] = dinv[i] * ( sum xd[src] + xd[i] )
//   L1: a   = A~ inp (3 feats);  h1 = relu(a@W1+b1)
//   L2: S   = A~ h1  (29 feats); h2 = relu(S@W2[:29] + a@W2[29:] + b2)
//   L3: s   = h2@W3[:29] + inp@W3[29:];  out = A~ s + b3   (scalar agg)
// CSR built per call.  h1 fp16 (64B/row).  ALL aggregations warp-per-node:
// agg29 half2 lanes (R9 pattern); agg3/agg1 lane-per-edge + butterfly reduce.
// degcnt self-restoring; nodes1 fused into scanA.  edge_index is int32.
// ----------------------------------------------------------------------------

#define MAXN 500000
#define MAXE 8000000

__device__ int    g_col[MAXE];
__device__ int    g_degcnt[MAXN];           // zero at entry, restored by scanA
__device__ int    g_rowptr[MAXN + 1];
__device__ int    g_cursor[MAXN];
__device__ int    g_blksum[1024];
__device__ int    g_blkoff[1024];
__device__ float  g_dinv[MAXN];
__device__ float4 g_xd[MAXN];               // dinv * [x0, x1, y1], pad
__device__ float4 g_a[MAXN];                // a = A~ inp, pad
__device__ uint4  g_h1h[(size_t)MAXN * 4];  // dinv*h1 as fp16, 32 halfs = 64B/row
__device__ float4 g_sagg[(size_t)MAXN * 8]; // A~ h1 fp32, padded to 32
__device__ float  g_sd[MAXN];               // dinv * s

// -------------------- K1: count in-degree (dst half of edge_index) ----------
__global__ void k_deg(const int* __restrict__ dst, int E) {
    int e4 = blockIdx.x * blockDim.x + threadIdx.x;
    int base = e4 * 4;
    if (base + 3 < E) {
        int4 d = *(const int4*)(dst + base);
        atomicAdd(&g_degcnt[d.x], 1);
        atomicAdd(&g_degcnt[d.y], 1);
        atomicAdd(&g_degcnt[d.z], 1);
        atomicAdd(&g_degcnt[d.w], 1);
    } else {
        for (int e = base; e < E; e++) atomicAdd(&g_degcnt[dst[e]], 1);
    }
}

// ------ Scan A (fused with node prep): exclusive scan + dinv/xd + restore ---
__global__ void k_scanA(const float* __restrict__ x, const float* __restrict__ y1, int N) {
    __shared__ int sh[1024];
    int t = threadIdx.x;
    int i = blockIdx.x * 1024 + t;
    int v = (i < N) ? g_degcnt[i] : 0;
    if (i < N) {
        g_degcnt[i] = 0;                       // restore invariant for next call
        float di = rsqrtf((float)(v + 1));     // +1 self loop
        g_dinv[i] = di;
        float2 xv = *(const float2*)(x + 2 * i);
        g_xd[i] = make_float4(di * xv.x, di * xv.y, di * y1[i], 0.f);
    }
    sh[t] = v;
    __syncthreads();
    for (int off = 1; off < 1024; off <<= 1) {
        int add = (t >= off) ? sh[t - off] : 0;
        __syncthreads();
        sh[t] += add;
        __syncthreads();
    }
    if (i < N) g_rowptr[i] = sh[t] - v;
    if (t == 1023) g_blksum[blockIdx.x] = sh[t];
}

// -------------------- Scan B: block sums (single block) ---------------------
__global__ void k_scanB(int NB) {
    __shared__ int sh[1024];
    int t = threadIdx.x;
    int v = (t < NB) ? g_blksum[t] : 0;
    sh[t] = v;
    __syncthreads();
    for (int off = 1; off < 1024; off <<= 1) {
        int add = (t >= off) ? sh[t - off] : 0;
        __syncthreads();
        sh[t] += add;
        __syncthreads();
    }
    if (t < NB) g_blkoff[t] = sh[t] - v;
}

// -------------------- Scan C: add offsets, init cursors ---------------------
__global__ void k_scanC(int N, int E) {
    int i = blockIdx.x * blockDim.x + threadIdx.x;
    if (i < N) {
        int rp = g_rowptr[i] + g_blkoff[i >> 10];
        g_rowptr[i] = rp;
        g_cursor[i] = rp;
    }
    if (i == 0) g_rowptr[N] = E;
}

// -------------------- K4: CSR fill (scalar, 1 edge/thread) ------------------
__global__ void k_fill(const int* __restrict__ src, const int* __restrict__ dst, int E) {
    int e = blockIdx.x * blockDim.x + threadIdx.x;
    if (e >= E) return;
    int d = dst[e];
    int p = atomicAdd(&g_cursor[d], 1);
    g_col[p] = src[e];
}

// ------ K5: 3-feat aggregation WARP-PER-NODE + fused GEMM1(relu), fp16 out --
__global__ void k_agg3(const float* __restrict__ W1, const float* __restrict__ b1, int N) {
    __shared__ float w1s[87];
    __shared__ float b1s[29];
    if (threadIdx.x < 87) w1s[threadIdx.x] = W1[threadIdx.x];
    if (threadIdx.x < 29) b1s[threadIdx.x] = b1[threadIdx.x];
    __syncthreads();

    int gt = blockIdx.x * blockDim.x + threadIdx.x;
    int i = gt >> 5;
    if (i >= N) return;
    int lane = gt & 31;

    int beg = g_rowptr[i], end = g_rowptr[i + 1];
    float s0 = 0.f, s1 = 0.f, s2 = 0.f;
    for (int t = beg; t < end; t += 32) {       // 1 iteration for deg<=32 (99.97%)
        int p = t + lane;
        if (p < end) {
            int c = __ldg(&g_col[p]);           // coalesced
            float4 v = __ldg(&g_xd[c]);         // 32 scattered 16B in flight
            s0 += v.x; s1 += v.y; s2 += v.z;
        }
    }
    // butterfly: all lanes end with the full sums
#pragma unroll
    for (int off = 16; off; off >>= 1) {
        s0 += __shfl_xor_sync(0xffffffffu, s0, off);
        s1 += __shfl_xor_sync(0xffffffffu, s1, off);
        s2 += __shfl_xor_sync(0xffffffffu, s2, off);
    }
    float4 sv = __ldg(&g_xd[i]);                // self term, broadcast
    float di = g_dinv[i];
    float a0 = di * (s0 + sv.x), a1 = di * (s1 + sv.y), a2 = di * (s2 + sv.z);
    if (lane == 0) g_a[i] = make_float4(a0, a1, a2, 0.f);

    // GEMM1: lane g<29 computes h[g] = di * relu(a . W1[:,g] + b1[g])
    float h = 0.f;
    if (lane < 29) {
        float hg = fmaf(a0, w1s[lane], fmaf(a1, w1s[29 + lane], fmaf(a2, w1s[58 + lane], b1s[lane])));
        h = di * fmaxf(hg, 0.f);
    }
    // pack pairs to fp16: lane q<16 stores (h[2q], h[2q+1])
    int q = lane & 15;
    float lo = __shfl_sync(0xffffffffu, h, 2 * q);
    float hi = __shfl_sync(0xffffffffu, h, 2 * q + 1);
    if (lane < 16) {
        __half2 t2 = __floats2half2_rn(lo, hi);
        unsigned* h1u = (unsigned*)g_h1h;
        h1u[(size_t)i * 16 + lane] = *reinterpret_cast<unsigned*>(&t2);   // 64B coalesced
    }
}

// ------ K6: 29-feat aggregation, warp/node, half2 lanes, 8 edges/warp/iter --
__global__ void k_agg29(int N) {
    int gt = blockIdx.x * blockDim.x + threadIdx.x;
    int i = gt >> 5;
    if (i >= N) return;
    int lane = gt & 31;
    int half = lane >> 4;        // 0 or 1: which edge of the pair
    int q = lane & 15;           // feature-pair index (2 halfs = 1 u32)
    const unsigned* h1u = (const unsigned*)g_h1h;   // 16 u32 per row
    int beg = g_rowptr[i], end = g_rowptr[i + 1];
    float di = g_dinv[i];

    float2 acc = make_float2(0.f, 0.f);
    if (half == 0) {             // self term handled by half 0
        unsigned su = h1u[(size_t)i * 16 + q];
        acc = __half22float2(*reinterpret_cast<__half2*>(&su));
    }
    int p = beg + half;          // my half's edge stream: beg+half, +2, +4, ...
    for (; p + 6 < end; p += 8) {    // 4 edges/half/iter = 8 edges/warp
        int c0 = __ldg(&g_col[p]);
        int c1 = __ldg(&g_col[p + 2]);
        int c2 = __ldg(&g_col[p + 4]);
        int c3 = __ldg(&g_col[p + 6]);
        unsigned u0 = __ldg(&h1u[(size_t)c0 * 16 + q]);
        unsigned u1 = __ldg(&h1u[(size_t)c1 * 16 + q]);
        unsigned u2 = __ldg(&h1u[(size_t)c2 * 16 + q]);
        unsigned u3 = __ldg(&h1u[(size_t)c3 * 16 + q]);
        float2 v0 = __half22float2(*reinterpret_cast<__half2*>(&u0));
        float2 v1 = __half22float2(*reinterpret_cast<__half2*>(&u1));
        float2 v2 = __half22float2(*reinterpret_cast<__half2*>(&u2));
        float2 v3 = __half22float2(*reinterpret_cast<__half2*>(&u3));
        acc.x += (v0.x + v1.x) + (v2.x + v3.x);
        acc.y += (v0.y + v1.y) + (v2.y + v3.y);
    }
    for (; p < end; p += 2) {
        int c = __ldg(&g_col[p]);
        unsigned u = __ldg(&h1u[(size_t)c * 16 + q]);
        float2 v = __half22float2(*reinterpret_cast<__half2*>(&u));
        acc.x += v.x; acc.y += v.y;
    }
    // combine the two halves
    acc.x += __shfl_xor_sync(0xffffffffu, acc.x, 16);
    acc.y += __shfl_xor_sync(0xffffffffu, acc.y, 16);
    if (half == 0) {
        float2* saggf2 = (float2*)g_sagg;
        saggf2[(size_t)i * 16 + q] = make_float2(di * acc.x, di * acc.y);
    }
}

// -------------------- K7: node GEMM2 (relu) + project to scalar s -----------
__global__ void k_gemm2(const float* __restrict__ x, const float* __restrict__ y1,
                        const float* __restrict__ W2, const float* __restrict__ b2,
                        const float* __restrict__ W3, int N) {
    __shared__ float w2s[928];
    __shared__ float b2s[29];
    __shared__ float w3s[32];
    for (int idx = threadIdx.x; idx < 928; idx += blockDim.x) w2s[idx] = W2[idx];
    if (threadIdx.x < 29) b2s[threadIdx.x] = b2[threadIdx.x];
    if (threadIdx.x < 32) w3s[threadIdx.x] = W3[threadIdx.x];
    __syncthreads();
    int i = blockIdx.x * blockDim.x + threadIdx.x;
    if (i >= N) return;

    float S[32];
    const float4* sp = &g_sagg[(size_t)i * 8];
#pragma unroll
    for (int q = 0; q < 8; q++) {
        float4 v = sp[q];
        S[4 * q] = v.x; S[4 * q + 1] = v.y; S[4 * q + 2] = v.z; S[4 * q + 3] = v.w;
    }
    float acc[29];
#pragma unroll
    for (int g = 0; g < 29; g++) acc[g] = b2s[g];
    for (int f = 0; f < 29; f++) {
        float v = S[f];
#pragma unroll
        for (int g = 0; g < 29; g++) acc[g] = fmaf(v, w2s[f * 29 + g], acc[g]);
    }
    float4 av = g_a[i];
#pragma unroll
    for (int g = 0; g < 29; g++) {
        acc[g] = fmaf(av.x, w2s[29 * 29 + g], acc[g]);
        acc[g] = fmaf(av.y, w2s[30 * 29 + g], acc[g]);
        acc[g] = fmaf(av.z, w2s[31 * 29 + g], acc[g]);
    }
    float s = 0.f;
#pragma unroll
    for (int g = 0; g < 29; g++) s = fmaf(fmaxf(acc[g], 0.f), w3s[g], s);
    s = fmaf(x[2 * i],     w3s[29], s);
    s = fmaf(x[2 * i + 1], w3s[30], s);
    s = fmaf(y1[i],        w3s[31], s);
    g_sd[i] = g_dinv[i] * s;
}

// ---------- K8: scalar aggregation WARP-PER-NODE + bias -> output -----------
__global__ void k_agg1(const float* __restrict__ b3, float* __restrict__ out, int N) {
    int gt = blockIdx.x * blockDim.x + threadIdx.x;
    int i = gt >> 5;
    if (i >= N) return;
    int lane = gt & 31;
    int beg = g_rowptr[i], end = g_rowptr[i + 1];

    float acc = 0.f;
    for (int t = beg; t < end; t += 32) {
        int p = t + lane;
        if (p < end) {
            int c = __ldg(&g_col[p]);
            acc += __ldg(&g_sd[c]);
        }
    }
#pragma unroll
    for (int off = 16; off; off >>= 1)
        acc += __shfl_xor_sync(0xffffffffu, acc, off);
    if (lane == 0) {
        acc += g_sd[i];                   // self term
        out[i] = fmaf(g_dinv[i], acc, __ldg(&b3[0]));
    }
}

// ----------------------------------------------------------------------------
extern "C" void kernel_launch(void* const* d_in, const int* in_sizes, int n_in,
                              void* d_out, int out_size) {
    const float* x  = (const float*)d_in[0];
    const float* y1 = (const float*)d_in[1];
    const int*   ei = (const int*)d_in[2];      // int32
    const float* W1 = (const float*)d_in[3];
    const float* b1 = (const float*)d_in[4];
    const float* W2 = (const float*)d_in[5];
    const float* b2 = (const float*)d_in[6];
    const float* W3 = (const float*)d_in[7];
    const float* b3 = (const float*)d_in[8];
    float* out = (float*)d_out;

    int N = in_sizes[1];        // y1 length
    int E = in_sizes[2] / 2;    // edge_index is [2, E]
    const int* src = ei;
    const int* dst = ei + E;

    const int TB = 256;
    int gN = (N + TB - 1) / TB;
    int gE = (E + TB - 1) / TB;
    int gE4 = ((E + 3) / 4 + TB - 1) / TB;
    int NB = (N + 1023) / 1024;
    int gW;   // warp-per-node grids
    {
        long long threads = (long long)N * 32;
        gW = (int)((threads + TB - 1) / TB);
    }

    k_deg   <<<gE4, TB>>>(dst, E);
    k_scanA <<<NB, 1024>>>(x, y1, N);
    k_scanB <<<1, 1024>>>(NB);
    k_scanC <<<gN, TB>>>(N, E);
    k_fill  <<<gE, TB>>>(src, dst, E);
    k_agg3  <<<gW, TB>>>(W1, b1, N);
    k_agg29 <<<gW, TB>>>(N);
    k_gemm2 <<<gN, TB>>>(x, y1, W2, b2, W3, N);
    k_agg1  <<<gW, TB>>>(b3, out, N);
}

// round 14
// speedup vs baseline: 1.3058x; 1.3058x over previous
#include <cuda_runtime.h>
#include <cuda_fp16.h>

// ----------------------------------------------------------------------------
// GCN-with-skip, 3 layers.  Algebra:
//   A~ x[i] = dinv[i] * ( sum_{e: dst=i} dinv[src] x[src]  +  dinv[i] x[i] )
// With xd = dinv * x:  A~ x[i] = dinv[i] * ( sum xd[src] + xd[i] )
//   L1: a   = A~ inp (3 feats);  h1 = relu(a@W1+b1)
//   L2: S   = A~ h1  (29 feats); h2 = relu(S@W2[:29] + a@W2[29:] + b2)
//   L3: s   = h2@W3[:29] + inp@W3[29:];  out = A~ s + b3   (scalar agg)
// CSR built per call.  h1 AND sagg stored fp16 (64B/row each, both L2-resident).
// agg29: warp/node, half2 lanes, 8 edges/warp/iter (best measured).
// agg3/agg1: thread-per-node (warp-per-node regressed in R13).
// degcnt self-restoring; nodes1 fused into scanA.  edge_index is int32.
// ----------------------------------------------------------------------------

#define MAXN 500000
#define MAXE 8000000

__device__ int    g_col[MAXE];
__device__ int    g_degcnt[MAXN];           // zero at entry, restored by scanA
__device__ int    g_rowptr[MAXN + 1];
__device__ int    g_cursor[MAXN];
__device__ int    g_blksum[1024];
__device__ int    g_blkoff[1024];
__device__ float  g_dinv[MAXN];
__device__ float4 g_xd[MAXN];               // dinv * [x0, x1, y1], pad
__device__ float4 g_a[MAXN];                // a = A~ inp, pad
__device__ uint4  g_h1h[(size_t)MAXN * 4];  // dinv*h1 fp16, 32 halfs = 64B/row
__device__ uint4  g_saggh[(size_t)MAXN * 4];// A~ h1 fp16, 32 halfs = 64B/row
__device__ float  g_sd[MAXN];               // dinv * s

// -------------------- K1: count in-degree (dst half of edge_index) ----------
__global__ void k_deg(const int* __restrict__ dst, int E) {
    int e4 = blockIdx.x * blockDim.x + threadIdx.x;
    int base = e4 * 4;
    if (base + 3 < E) {
        int4 d = *(const int4*)(dst + base);
        atomicAdd(&g_degcnt[d.x], 1);
        atomicAdd(&g_degcnt[d.y], 1);
        atomicAdd(&g_degcnt[d.z], 1);
        atomicAdd(&g_degcnt[d.w], 1);
    } else {
        for (int e = base; e < E; e++) atomicAdd(&g_degcnt[dst[e]], 1);
    }
}

// ------ Scan A (fused with node prep): exclusive scan + dinv/xd + restore ---
__global__ void k_scanA(const float* __restrict__ x, const float* __restrict__ y1, int N) {
    __shared__ int sh[1024];
    int t = threadIdx.x;
    int i = blockIdx.x * 1024 + t;
    int v = (i < N) ? g_degcnt[i] : 0;
    if (i < N) {
        g_degcnt[i] = 0;                       // restore invariant for next call
        float di = rsqrtf((float)(v + 1));     // +1 self loop
        g_dinv[i] = di;
        float2 xv = *(const float2*)(x + 2 * i);
        g_xd[i] = make_float4(di * xv.x, di * xv.y, di * y1[i], 0.f);
    }
    sh[t] = v;
    __syncthreads();
    for (int off = 1; off < 1024; off <<= 1) {
        int add = (t >= off) ? sh[t - off] : 0;
        __syncthreads();
        sh[t] += add;
        __syncthreads();
    }
    if (i < N) g_rowptr[i] = sh[t] - v;
    if (t == 1023) g_blksum[blockIdx.x] = sh[t];
}

// -------------------- Scan B: block sums (single block) ---------------------
__global__ void k_scanB(int NB) {
    __shared__ int sh[1024];
    int t = threadIdx.x;
    int v = (t < NB) ? g_blksum[t] : 0;
    sh[t] = v;
    __syncthreads();
    for (int off = 1; off < 1024; off <<= 1) {
        int add = (t >= off) ? sh[t - off] : 0;
        __syncthreads();
        sh[t] += add;
        __syncthreads();
    }
    if (t < NB) g_blkoff[t] = sh[t] - v;
}

// -------------------- Scan C: add offsets, init cursors ---------------------
__global__ void k_scanC(int N, int E) {
    int i = blockIdx.x * blockDim.x + threadIdx.x;
    if (i < N) {
        int rp = g_rowptr[i] + g_blkoff[i >> 10];
        g_rowptr[i] = rp;
        g_cursor[i] = rp;
    }
    if (i == 0) g_rowptr[N] = E;
}

// -------------------- K4: CSR fill (scalar, 1 edge/thread) ------------------
__global__ void k_fill(const int* __restrict__ src, const int* __restrict__ dst, int E) {
    int e = blockIdx.x * blockDim.x + threadIdx.x;
    if (e >= E) return;
    int d = dst[e];
    int p = atomicAdd(&g_cursor[d], 1);
    g_col[p] = src[e];
}

// -------------------- K5: 3-feat aggregation + fused GEMM1(relu), fp16 out --
__global__ void k_agg3(const float* __restrict__ W1, const float* __restrict__ b1, int N) {
    __shared__ float w1s[87];
    __shared__ float b1s[29];
    int t = threadIdx.x;
    if (t < 87) w1s[t] = W1[t];
    if (t < 29) b1s[t] = b1[t];
    __syncthreads();
    int i = blockIdx.x * blockDim.x + t;
    if (i >= N) return;

    int beg = g_rowptr[i], end = g_rowptr[i + 1];
    float4 sv = g_xd[i];                 // self term
    float s0 = sv.x, s1 = sv.y, s2 = sv.z;
    int p = beg;
    for (; p + 3 < end; p += 4) {
        int c0 = __ldg(&g_col[p]);
        int c1 = __ldg(&g_col[p + 1]);
        int c2 = __ldg(&g_col[p + 2]);
        int c3 = __ldg(&g_col[p + 3]);
        float4 v0 = __ldg(&g_xd[c0]);
        float4 v1 = __ldg(&g_xd[c1]);
        float4 v2 = __ldg(&g_xd[c2]);
        float4 v3 = __ldg(&g_xd[c3]);
        s0 += (v0.x + v1.x) + (v2.x + v3.x);
        s1 += (v0.y + v1.y) + (v2.y + v3.y);
        s2 += (v0.z + v1.z) + (v2.z + v3.z);
    }
    for (; p < end; p++) {
        float4 v = __ldg(&g_xd[__ldg(&g_col[p])]);
        s0 += v.x; s1 += v.y; s2 += v.z;
    }
    float di = g_dinv[i];
    float a0 = di * s0, a1 = di * s1, a2 = di * s2;
    g_a[i] = make_float4(a0, a1, a2, 0.f);

    float h[32];
#pragma unroll
    for (int g = 0; g < 29; g++) {
        float hg = fmaf(a0, w1s[g], fmaf(a1, w1s[29 + g], fmaf(a2, w1s[58 + g], b1s[g])));
        h[g] = di * fmaxf(hg, 0.f);      // store dinv*relu(...)
    }
    h[29] = 0.f; h[30] = 0.f; h[31] = 0.f;

    unsigned u[16];
#pragma unroll
    for (int q = 0; q < 16; q++) {
        __half2 t2 = __floats2half2_rn(h[2 * q], h[2 * q + 1]);
        u[q] = *reinterpret_cast<unsigned*>(&t2);
    }
    uint4* dst = &g_h1h[(size_t)i * 4];
    dst[0] = make_uint4(u[0],  u[1],  u[2],  u[3]);
    dst[1] = make_uint4(u[4],  u[5],  u[6],  u[7]);
    dst[2] = make_uint4(u[8],  u[9],  u[10], u[11]);
    dst[3] = make_uint4(u[12], u[13], u[14], u[15]);
}

// ------ K6: 29-feat aggregation, warp/node, half2 lanes, 8 edges/warp/iter --
__global__ void k_agg29(int N) {
    int gt = blockIdx.x * blockDim.x + threadIdx.x;
    int i = gt >> 5;
    if (i >= N) return;
    int lane = gt & 31;
    int half = lane >> 4;        // 0 or 1: which edge of the pair
    int q = lane & 15;           // feature-pair index (2 halfs = 1 u32)
    const unsigned* h1u = (const unsigned*)g_h1h;   // 16 u32 per row
    int beg = g_rowptr[i], end = g_rowptr[i + 1];
    float di = g_dinv[i];

    float2 acc = make_float2(0.f, 0.f);
    if (half == 0) {             // self term handled by half 0
        unsigned su = h1u[(size_t)i * 16 + q];
        acc = __half22float2(*reinterpret_cast<__half2*>(&su));
    }
    int p = beg + half;          // my half's edge stream: beg+half, +2, +4, ...
    for (; p + 6 < end; p += 8) {    // 4 edges/half/iter = 8 edges/warp
        int c0 = __ldg(&g_col[p]);
        int c1 = __ldg(&g_col[p + 2]);
        int c2 = __ldg(&g_col[p + 4]);
        int c3 = __ldg(&g_col[p + 6]);
        unsigned u0 = __ldg(&h1u[(size_t)c0 * 16 + q]);
        unsigned u1 = __ldg(&h1u[(size_t)c1 * 16 + q]);
        unsigned u2 = __ldg(&h1u[(size_t)c2 * 16 + q]);
        unsigned u3 = __ldg(&h1u[(size_t)c3 * 16 + q]);
        float2 v0 = __half22float2(*reinterpret_cast<__half2*>(&u0));
        float2 v1 = __half22float2(*reinterpret_cast<__half2*>(&u1));
        float2 v2 = __half22float2(*reinterpret_cast<__half2*>(&u2));
        float2 v3 = __half22float2(*reinterpret_cast<__half2*>(&u3));
        acc.x += (v0.x + v1.x) + (v2.x + v3.x);
        acc.y += (v0.y + v1.y) + (v2.y + v3.y);
    }
    for (; p < end; p += 2) {
        int c = __ldg(&g_col[p]);
        unsigned u = __ldg(&h1u[(size_t)c * 16 + q]);
        float2 v = __half22float2(*reinterpret_cast<__half2*>(&u));
        acc.x += v.x; acc.y += v.y;
    }
    // combine the two halves
    acc.x += __shfl_xor_sync(0xffffffffu, acc.x, 16);
    acc.y += __shfl_xor_sync(0xffffffffu, acc.y, 16);
    if (half == 0) {
        __half2 hv = __floats2half2_rn(di * acc.x, di * acc.y);
        unsigned* sg = (unsigned*)g_saggh;
        sg[(size_t)i * 16 + q] = *reinterpret_cast<unsigned*>(&hv);   // 64B coalesced
    }
}

// -------------------- K7: node GEMM2 (relu) + project to scalar s -----------
__global__ void k_gemm2(const float* __restrict__ x, const float* __restrict__ y1,
                        const float* __restrict__ W2, const float* __restrict__ b2,
                        const float* __restrict__ W3, int N) {
    __shared__ float w2s[928];
    __shared__ float b2s[29];
    __shared__ float w3s[32];
    for (int idx = threadIdx.x; idx < 928; idx += blockDim.x) w2s[idx] = W2[idx];
    if (threadIdx.x < 29) b2s[threadIdx.x] = b2[threadIdx.x];
    if (threadIdx.x < 32) w3s[threadIdx.x] = W3[threadIdx.x];
    __syncthreads();
    int i = blockIdx.x * blockDim.x + threadIdx.x;
    if (i >= N) return;

    float S[32];
    const uint4* sp = &g_saggh[(size_t)i * 4];
#pragma unroll
    for (int r = 0; r < 4; r++) {
        uint4 u = sp[r];
        unsigned w[4] = {u.x, u.y, u.z, u.w};
#pragma unroll
        for (int k = 0; k < 4; k++) {
            float2 f = __half22float2(*reinterpret_cast<__half2*>(&w[k]));
            S[r * 8 + 2 * k]     = f.x;
            S[r * 8 + 2 * k + 1] = f.y;
        }
    }
    float acc[29];
#pragma unroll
    for (int g = 0; g < 29; g++) acc[g] = b2s[g];
    for (int f = 0; f < 29; f++) {
        float v = S[f];
#pragma unroll
        for (int g = 0; g < 29; g++) acc[g] = fmaf(v, w2s[f * 29 + g], acc[g]);
    }
    float4 av = g_a[i];
#pragma unroll
    for (int g = 0; g < 29; g++) {
        acc[g] = fmaf(av.x, w2s[29 * 29 + g], acc[g]);
        acc[g] = fmaf(av.y, w2s[30 * 29 + g], acc[g]);
        acc[g] = fmaf(av.z, w2s[31 * 29 + g], acc[g]);
    }
    float s = 0.f;
#pragma unroll
    for (int g = 0; g < 29; g++) s = fmaf(fmaxf(acc[g], 0.f), w3s[g], s);
    s = fmaf(x[2 * i],     w3s[29], s);
    s = fmaf(x[2 * i + 1], w3s[30], s);
    s = fmaf(y1[i],        w3s[31], s);
    g_sd[i] = g_dinv[i] * s;
}

// -------------------- K8: scalar aggregation + bias -> output ---------------
__global__ void k_agg1(const float* __restrict__ b3, float* __restrict__ out, int N) {
    int i = blockIdx.x * blockDim.x + threadIdx.x;
    if (i >= N) return;
    int beg = g_rowptr[i], end = g_rowptr[i + 1];
    float acc = g_sd[i];                  // self term
    int p = beg;
    for (; p + 7 < end; p += 8) {
        int c0 = __ldg(&g_col[p]);
        int c1 = __ldg(&g_col[p + 1]);
        int c2 = __ldg(&g_col[p + 2]);
        int c3 = __ldg(&g_col[p + 3]);
        int c4 = __ldg(&g_col[p + 4]);
        int c5 = __ldg(&g_col[p + 5]);
        int c6 = __ldg(&g_col[p + 6]);
        int c7 = __ldg(&g_col[p + 7]);
        float a0 = __ldg(&g_sd[c0]) + __ldg(&g_sd[c1]);
        float a1 = __ldg(&g_sd[c2]) + __ldg(&g_sd[c3]);
        float a2 = __ldg(&g_sd[c4]) + __ldg(&g_sd[c5]);
        float a3 = __ldg(&g_sd[c6]) + __ldg(&g_sd[c7]);
        acc += (a0 + a1) + (a2 + a3);
    }
    for (; p < end; p++) acc += __ldg(&g_sd[__ldg(&g_col[p])]);
    out[i] = fmaf(g_dinv[i], acc, __ldg(&b3[0]));
}

// ----------------------------------------------------------------------------
extern "C" void kernel_launch(void* const* d_in, const int* in_sizes, int n_in,
                              void* d_out, int out_size) {
    const float* x  = (const float*)d_in[0];
    const float* y1 = (const float*)d_in[1];
    const int*   ei = (const int*)d_in[2];      // int32
    const float* W1 = (const float*)d_in[3];
    const float* b1 = (const float*)d_in[4];
    const float* W2 = (const float*)d_in[5];
    const float* b2 = (const float*)d_in[6];
    const float* W3 = (const float*)d_in[7];
    const float* b3 = (const float*)d_in[8];
    float* out = (float*)d_out;

    int N = in_sizes[1];        // y1 length
    int E = in_sizes[2] / 2;    // edge_index is [2, E]
    const int* src = ei;
    const int* dst = ei + E;

    const int TB = 256;
    int gN = (N + TB - 1) / TB;
    int gE = (E + TB - 1) / TB;
    int gE4 = ((E + 3) / 4 + TB - 1) / TB;
    int NB = (N + 1023) / 1024;

    k_deg   <<<gE4, TB>>>(dst, E);
    k_scanA <<<NB, 1024>>>(x, y1, N);
    k_scanB <<<1, 1024>>>(NB);
    k_scanC <<<gN, TB>>>(N, E);
    k_fill  <<<gE, TB>>>(src, dst, E);
    k_agg3  <<<gN, TB>>>(W1, b1, N);
    {
        long long threads = (long long)N * 32;
        int grid = (int)((threads + TB - 1) / TB);
        k_agg29<<<grid, TB>>>(N);
    }
    k_gemm2 <<<gN, TB>>>(x, y1, W2, b2, W3, N);
    k_agg1  <<<gN, TB>>>(b3, out, N);
}